// round 4
// baseline (speedup 1.0000x reference)
#include <cuda_runtime.h>

#define P 576
#define V (P / 4)          // 144 float4 per row
#define NC 3
#define KDIM 4
#define THREADS 576
#define GRID 444           // 3 CTAs/SM * 148 SMs = one full wave

__device__ float g_sum[P];    // zero-initialized at load; re-zeroed by project kernel
__device__ float g_sumsq[P];

__global__ __launch_bounds__(THREADS) void csoap_reduce_kernel(
    const float4* __restrict__ X4, int n_rows, int rows_per_block)
{
    const int c = threadIdx.x % V;   // float4 column 0..143
    const int q = threadIdx.x / V;   // row phase 0..3

    int r0 = blockIdx.x * rows_per_block;
    int r1 = r0 + rows_per_block;
    if (r1 > n_rows) r1 = n_rows;

    float4 s  = make_float4(0.f, 0.f, 0.f, 0.f);
    float4 s2 = make_float4(0.f, 0.f, 0.f, 0.f);

    int r = r0 + q;
    // 2-deep unroll: two LDG.128 in flight per thread
    for (; r + 4 < r1; r += 8) {
        float4 a = __ldcs(X4 + (size_t)r * V + c);
        float4 b = __ldcs(X4 + (size_t)(r + 4) * V + c);
        s.x += a.x; s.y += a.y; s.z += a.z; s.w += a.w;
        s2.x = fmaf(a.x, a.x, s2.x); s2.y = fmaf(a.y, a.y, s2.y);
        s2.z = fmaf(a.z, a.z, s2.z); s2.w = fmaf(a.w, a.w, s2.w);
        s.x += b.x; s.y += b.y; s.z += b.z; s.w += b.w;
        s2.x = fmaf(b.x, b.x, s2.x); s2.y = fmaf(b.y, b.y, s2.y);
        s2.z = fmaf(b.z, b.z, s2.z); s2.w = fmaf(b.w, b.w, s2.w);
    }
    for (; r < r1; r += 4) {
        float4 a = __ldcs(X4 + (size_t)r * V + c);
        s.x += a.x; s.y += a.y; s.z += a.z; s.w += a.w;
        s2.x = fmaf(a.x, a.x, s2.x); s2.y = fmaf(a.y, a.y, s2.y);
        s2.z = fmaf(a.z, a.z, s2.z); s2.w = fmaf(a.w, a.w, s2.w);
    }

    // block reduction across the 4 row phases, then 8 atomics per float4-col
    __shared__ float4 sh_s[THREADS];
    __shared__ float4 sh_s2[THREADS];
    sh_s[threadIdx.x]  = s;
    sh_s2[threadIdx.x] = s2;
    __syncthreads();

    if (threadIdx.x < V) {
        float4 ts  = sh_s[threadIdx.x];
        float4 ts2 = sh_s2[threadIdx.x];
        #pragma unroll
        for (int qq = 1; qq < 4; qq++) {
            float4 o  = sh_s[threadIdx.x + qq * V];
            float4 o2 = sh_s2[threadIdx.x + qq * V];
            ts.x += o.x;  ts.y += o.y;  ts.z += o.z;  ts.w += o.w;
            ts2.x += o2.x; ts2.y += o2.y; ts2.z += o2.z; ts2.w += o2.w;
        }
        int col = threadIdx.x * 4;
        atomicAdd(&g_sum[col + 0], ts.x);
        atomicAdd(&g_sum[col + 1], ts.y);
        atomicAdd(&g_sum[col + 2], ts.z);
        atomicAdd(&g_sum[col + 3], ts.w);
        atomicAdd(&g_sumsq[col + 0], ts2.x);
        atomicAdd(&g_sumsq[col + 1], ts2.y);
        atomicAdd(&g_sumsq[col + 2], ts2.z);
        atomicAdd(&g_sumsq[col + 3], ts2.w);
    }
}

// Single block: finalize cumulants, subtract mu, project with W (1728 x 4),
// then re-zero the accumulators for the next graph replay.
__global__ __launch_bounds__(P) void csoap_project_kernel(
    const float* __restrict__ mu, const float* __restrict__ W,
    float* __restrict__ out, float inv_n)
{
    __shared__ float s_acc[KDIM];
    const int j = threadIdx.x;   // column index, 0..575

    if (j < KDIM) s_acc[j] = 0.0f;
    __syncthreads();

    float m    = g_sum[j] * inv_n;
    float mom2 = fmaf(-m, m, g_sumsq[j] * inv_n);  // E[x^2] - m^2

    // re-zero for next replay (invariant: accumulators are zero between launches)
    g_sum[j]   = 0.0f;
    g_sumsq[j] = 0.0f;

    int jb = j * NC;
    float d0 = m    - mu[jb + 0];
    float d1 = 0.0f - mu[jb + 1];
    float d2 = mom2 - mu[jb + 2];

    float acc[KDIM];
    #pragma unroll
    for (int k = 0; k < KDIM; k++) {
        acc[k] = d0 * W[(jb + 0) * KDIM + k]
               + d1 * W[(jb + 1) * KDIM + k]
               + d2 * W[(jb + 2) * KDIM + k];
    }

    #pragma unroll
    for (int k = 0; k < KDIM; k++) {
        float v = acc[k];
        #pragma unroll
        for (int off = 16; off > 0; off >>= 1)
            v += __shfl_down_sync(0xFFFFFFFFu, v, off);
        if ((threadIdx.x & 31) == 0)
            atomicAdd(&s_acc[k], v);
    }
    __syncthreads();

    if (j < KDIM) out[j] = s_acc[j];
}

extern "C" void kernel_launch(void* const* d_in, const int* in_sizes, int n_in,
                              void* d_out, int out_size)
{
    const float4* X4 = (const float4*)d_in[0];
    const float* mu  = (const float*)d_in[1];
    const float* W   = (const float*)d_in[2];
    float* out = (float*)d_out;

    int n_rows = in_sizes[0] / P;
    int rows_per_block = (n_rows + GRID - 1) / GRID;

    csoap_reduce_kernel<<<GRID, THREADS>>>(X4, n_rows, rows_per_block);
    csoap_project_kernel<<<1, P>>>(mu, W, out, 1.0f / (float)n_rows);
}

// round 5
// speedup vs baseline: 1.1063x; 1.1063x over previous
#include <cuda_runtime.h>

#define P 576
#define NC 3
#define KDIM 4
#define THREADS 576
#define GRID 592

__device__ float g_sum[P];      // zero at load; reset by last block each run
__device__ float g_sumsq[P];
__device__ unsigned int g_ticket;  // zero at load; reset by last block

__global__ __launch_bounds__(THREADS) void csoap_fused_kernel(
    const float* __restrict__ X,
    const float* __restrict__ mu,
    const float* __restrict__ W,
    float* __restrict__ out,
    int n_rows, int rows_per_block, float inv_n)
{
    const int col = threadIdx.x;

    int r0 = blockIdx.x * rows_per_block;
    int r1 = r0 + rows_per_block;
    if (r1 > n_rows) r1 = n_rows;

    // ---- per-column accumulation (R1-proven layout: thread owns one column,
    //      consecutive rows, 4-way unroll, perfectly coalesced LDG.32) ----
    float s = 0.0f, s2 = 0.0f;
    if (r0 < r1) {
        const float* p = X + (size_t)r0 * P + col;
        int r = r0;
        for (; r + 4 <= r1; r += 4) {
            float a0 = p[0 * P];
            float a1 = p[1 * P];
            float a2 = p[2 * P];
            float a3 = p[3 * P];
            p += 4 * P;
            s  += (a0 + a1) + (a2 + a3);
            s2 += (a0 * a0 + a1 * a1) + (a2 * a2 + a3 * a3);
        }
        for (; r < r1; r++) {
            float a = p[0];
            p += P;
            s  += a;
            s2 += a * a;
        }
        atomicAdd(&g_sum[col],   s);
        atomicAdd(&g_sumsq[col], s2);
    }

    // ---- last-block election ----
    __threadfence();
    __syncthreads();
    __shared__ int is_last;
    if (threadIdx.x == 0)
        is_last = (atomicAdd(&g_ticket, 1u) == (unsigned)(gridDim.x - 1));
    __syncthreads();

    if (!is_last) return;

    // ---- finalize + project (576 threads, one per feature column) ----
    __shared__ float s_acc[KDIM];
    const int j = threadIdx.x;
    if (j < KDIM) s_acc[j] = 0.0f;
    __syncthreads();

    float total   = __ldcg(&g_sum[j]);     // L2 read, bypass L1
    float totalsq = __ldcg(&g_sumsq[j]);
    float m    = total * inv_n;
    float mom2 = fmaf(-m, m, totalsq * inv_n);   // E[x^2] - m^2

    // reset scratch for the next graph replay
    g_sum[j]   = 0.0f;
    g_sumsq[j] = 0.0f;
    if (j == 0) g_ticket = 0u;

    int jb = j * NC;
    float d0 = m    - mu[jb + 0];
    float d1 = 0.0f - mu[jb + 1];
    float d2 = mom2 - mu[jb + 2];

    float acc[KDIM];
    #pragma unroll
    for (int k = 0; k < KDIM; k++) {
        acc[k] = d0 * W[(jb + 0) * KDIM + k]
               + d1 * W[(jb + 1) * KDIM + k]
               + d2 * W[(jb + 2) * KDIM + k];
    }

    #pragma unroll
    for (int k = 0; k < KDIM; k++) {
        float v = acc[k];
        #pragma unroll
        for (int off = 16; off > 0; off >>= 1)
            v += __shfl_down_sync(0xFFFFFFFFu, v, off);
        if ((threadIdx.x & 31) == 0)
            atomicAdd(&s_acc[k], v);
    }
    __syncthreads();

    if (j < KDIM) out[j] = s_acc[j];
}

extern "C" void kernel_launch(void* const* d_in, const int* in_sizes, int n_in,
                              void* d_out, int out_size)
{
    const float* X  = (const float*)d_in[0];
    const float* mu = (const float*)d_in[1];
    const float* W  = (const float*)d_in[2];
    float* out = (float*)d_out;

    int n_rows = in_sizes[0] / P;
    int rows_per_block = (n_rows + GRID - 1) / GRID;

    csoap_fused_kernel<<<GRID, THREADS>>>(X, mu, W, out, n_rows,
                                          rows_per_block, 1.0f / (float)n_rows);
}